// round 13
// baseline (speedup 1.0000x reference)
#include <cuda_runtime.h>
#include <string.h>

#define ALPHA 0.2f
#define EPS   1e-5f
#define BB    8
#define NN    2048
#define FF    128
#define PD    258   // k1 dup pitch
#define PS    132   // k1 plain pitch
#define PSP   129   // k2 Pt pitch (odd -> conflict-free phase-A stores; scalar reads ok)
#define PSW   132   // k2 Whs pitch (16B-aligned rows for LDS.128)

typedef unsigned long long ull;
typedef unsigned int uint;

// Scratch (no allocation allowed)
__device__ float g_Wh [BB * NN * FF];
__device__ float g_Wh1[BB * NN];
__device__ float g_Wh2[BB * NN];

__device__ __forceinline__ void fma2(ull& d, ull a, ull b) {
    asm("fma.rn.f32x2 %0, %1, %2, %0;" : "+l"(d) : "l"(a), "l"(b));
}
__device__ __forceinline__ ull splat2(float w) {
    ull d; asm("mov.b64 %0, {%1, %1};" : "=l"(d) : "f"(w)); return d;
}
__device__ __forceinline__ float2 asf2(ull v) { float2 f; memcpy(&f, &v, 8); return f; }
__device__ __forceinline__ ull    asu2(float2 f) { ull v; memcpy(&v, &f, 8); return v; }
__device__ __forceinline__ uint smem_u32(const void* p) {
    uint a; asm("{ .reg .u64 t; cvta.to.shared.u64 t, %1; cvt.u32.u64 %0, t; }" : "=r"(a) : "l"(p));
    return a;
}
__device__ __forceinline__ void cp_async16(uint dst, const void* src) {
    asm volatile("cp.async.cg.shared.global [%0], [%1], 16;" :: "r"(dst), "l"(src) : "memory");
}

// ---------------------------------------------------------------------------
// Kernel 1: Wh = h @ W^T + b ; Wh1 = Wh@a[:128]; Wh2 = Wh@a[128:]  (FFMA2)
// (unchanged — ~20 us, measured)
// ---------------------------------------------------------------------------
__global__ __launch_bounds__(256) void gat_k1(const float* __restrict__ h,
                                              const float* __restrict__ W,
                                              const float* __restrict__ bias,
                                              const float* __restrict__ aw) {
    extern __shared__ float sm[];
    float* hTd = sm;             // [128 f][PD]
    float* Wt  = sm + 128 * PD;  // [128 f][PS]

    int tid = threadIdx.x;
    int r = tid >> 4, c = tid & 15;
    int row0 = blockIdx.x * 128;

    for (int idx = tid; idx < FF * FF; idx += 256) {
        int o = idx >> 7, f = idx & 127;
        Wt[f * PS + o] = W[idx];
    }
    #pragma unroll
    for (int e = 0; e < 16; e++) {
        int idx = e * 256 + tid;
        int i = idx >> 5, m = idx & 31;
        float4 v = ((const float4*)(h + (size_t)(row0 + i) * FF))[m];
        float2 d;
        d.x = d.y = v.x; *(float2*)(hTd + (4*m+0) * PD + 2*i) = d;
        d.x = d.y = v.y; *(float2*)(hTd + (4*m+1) * PD + 2*i) = d;
        d.x = d.y = v.z; *(float2*)(hTd + (4*m+2) * PD + 2*i) = d;
        d.x = d.y = v.w; *(float2*)(hTd + (4*m+3) * PD + 2*i) = d;
    }
    __syncthreads();

    ull acc[8][4];
    #pragma unroll
    for (int k = 0; k < 4; k++) {
        float2 bp = *(const float2*)(bias + 2*c + 32*k);
        ull bu = asu2(bp);
        #pragma unroll
        for (int u = 0; u < 8; u++) acc[u][k] = bu;
    }

    const float* Bm = Wt + 2 * c;
    #pragma unroll 2
    for (int f = 0; f < 128; f++) {
        ull pv[8], wv[4];
        #pragma unroll
        for (int u = 0; u < 8; u++)
            pv[u] = *(const ull*)(hTd + f * PD + 2 * (r + 16 * u));
        #pragma unroll
        for (int k = 0; k < 4; k++)
            wv[k] = *(const ull*)(Bm + f * PS + 32 * k);
        #pragma unroll
        for (int u = 0; u < 8; u++)
            #pragma unroll
            for (int k = 0; k < 4; k++)
                fma2(acc[u][k], pv[u], wv[k]);
    }

    float2 a1[4], a2[4];
    #pragma unroll
    for (int k = 0; k < 4; k++) {
        a1[k] = *(const float2*)(aw + 2*c + 32*k);
        a2[k] = *(const float2*)(aw + FF + 2*c + 32*k);
    }

    #pragma unroll
    for (int u = 0; u < 8; u++) {
        int row = row0 + r + 16 * u;
        float s1 = 0.f, s2 = 0.f;
        #pragma unroll
        for (int k = 0; k < 4; k++) {
            float2 v = asf2(acc[u][k]);
            *(float2*)(g_Wh + (size_t)row * FF + 2*c + 32*k) = v;
            s1 = fmaf(v.x, a1[k].x, fmaf(v.y, a1[k].y, s1));
            s2 = fmaf(v.x, a2[k].x, fmaf(v.y, a2[k].y, s2));
        }
        #pragma unroll
        for (int d = 1; d < 16; d <<= 1) {
            s1 += __shfl_xor_sync(0xffffffffu, s1, d);
            s2 += __shfl_xor_sync(0xffffffffu, s2, d);
        }
        if (c == 0) { g_Wh1[row] = s1; g_Wh2[row] = s2; }
    }
}

// ---------------------------------------------------------------------------
// Kernel 2 (512 threads): software-pipelined fused GAT core.
// Column permutation pi(j) = (j&3)*32 + (j>>2) applied to BOTH Pt and Whs
// (sum over j commutes) -> adj prefetched as int4 (8x LDG.128, MLP 8) with
// conflict-free Pt stores; Whs double-buffered + filled via cp.async for
// tile jt+1 while phase B of tile jt runs. Phase B mapping = R12 (measured).
// ---------------------------------------------------------------------------
__global__ __launch_bounds__(512) void gat_k2(const int* __restrict__ adj,
                                              float* __restrict__ out) {
    extern __shared__ float sm[];
    float* Pt   = sm;                          // [128 d][PSP]
    float* WhsB[2];
    WhsB[0] = sm + 128 * PSP;                  // [128 d][PSW]
    WhsB[1] = sm + 128 * PSP + 128 * PSW;
    __shared__ float Wh1s[128];
    __shared__ float rs[128];

    int tid  = threadIdx.x;
    int b    = blockIdx.x >> 4;
    int it   = blockIdx.x & 15;
    int r    = tid >> 4, c = tid & 15;     // phase-B mapping (unchanged)
    int warp = tid >> 5, lane = tid & 31;

    if (tid < 128) Wh1s[tid] = g_Wh1[b * NN + it * 128 + tid];

    ull acc[4][4];
    #pragma unroll
    for (int u = 0; u < 4; u++)
        #pragma unroll
        for (int k = 0; k < 4; k++) acc[u][k] = 0ULL;
    float rsum[8];
    #pragma unroll
    for (int s = 0; s < 8; s++) rsum[s] = 0.f;

    const size_t adjBase = ((size_t)b * NN + it * 128) * NN;
    const float4* WhgB   = (const float4*)(g_Wh + (size_t)b * NN * FF);

    // cp.async destination rows: thread covers idx=e*512+tid -> dst row d, seg m.
    // src j = 4*(d&31) + (d>>5)  (pi^-1)
    uint whsAddr[2];
    whsAddr[0] = smem_u32(WhsB[0]);
    whsAddr[1] = smem_u32(WhsB[1]);

    // ---- prologue: adj(0)+wh2(0) regs; cp.async Whs[0] ----
    int4  aj[8];
    float4 wh2r;
    #pragma unroll
    for (int s = 0; s < 8; s++)
        aj[s] = *(const int4*)(adj + adjBase + (size_t)(s * 16 + warp) * NN + 4 * lane);
    wh2r = *(const float4*)(g_Wh2 + b * NN + 4 * lane);
    #pragma unroll
    for (int e = 0; e < 8; e++) {
        int idx = e * 512 + tid;
        int d = idx >> 5, m = idx & 31;
        int j = 4 * (d & 31) + (d >> 5);
        cp_async16(whsAddr[0] + (uint)((d * PSW + 4 * m) * 4), WhgB + (size_t)j * 32 + m);
    }
    asm volatile("cp.async.commit_group;" ::: "memory");

    __syncthreads();   // Wh1s visible

    for (int jt = 0; jt < 16; jt++) {
        // ---- phase A: pure compute from prefetched regs ----
        #pragma unroll
        for (int s = 0; s < 8; s++) {
            int li = s * 16 + warp;
            float wh1 = Wh1s[li];
            int4 av = aj[s];
            float s0 = wh1 + wh2r.x; s0 = (s0 >= 0.f) ? s0 : ALPHA * s0;
            float s1 = wh1 + wh2r.y; s1 = (s1 >= 0.f) ? s1 : ALPHA * s1;
            float s2 = wh1 + wh2r.z; s2 = (s2 >= 0.f) ? s2 : ALPHA * s2;
            float s3 = wh1 + wh2r.w; s3 = (s3 >= 0.f) ? s3 : ALPHA * s3;
            float p0 = av.x ? __expf(s0) : 0.f;
            float p1 = av.y ? __expf(s1) : 0.f;
            float p2 = av.z ? __expf(s2) : 0.f;
            float p3 = av.w ? __expf(s3) : 0.f;
            rsum[s] += (p0 + p1) + (p2 + p3);
            // dst rows: d = lane + 32k  (pi(4*lane+k)) -> banks (lane+li): conflict-free
            Pt[(lane +  0) * PSP + li] = p0;
            Pt[(lane + 32) * PSP + li] = p1;
            Pt[(lane + 64) * PSP + li] = p2;
            Pt[(lane + 96) * PSP + li] = p3;
        }

        // ---- prefetch tile jt+1 (adj regs + wh2 regs + cp.async Whs) ----
        if (jt < 15) {
            const int* ap = adj + adjBase + (size_t)(jt + 1) * 128 + 4 * lane;
            #pragma unroll
            for (int s = 0; s < 8; s++)
                aj[s] = *(const int4*)(ap + (size_t)(s * 16 + warp) * NN);
            wh2r = *(const float4*)(g_Wh2 + b * NN + (jt + 1) * 128 + 4 * lane);
            const float4* Whg = WhgB + (size_t)(jt + 1) * 128 * 32;
            uint dstb = whsAddr[(jt + 1) & 1];
            #pragma unroll
            for (int e = 0; e < 8; e++) {
                int idx = e * 512 + tid;
                int d = idx >> 5, m = idx & 31;
                int j = 4 * (d & 31) + (d >> 5);
                cp_async16(dstb + (uint)((d * PSW + 4 * m) * 4), Whg + (size_t)j * 32 + m);
            }
            asm volatile("cp.async.commit_group;" ::: "memory");
            asm volatile("cp.async.wait_group 1;" ::: "memory");
        } else {
            asm volatile("cp.async.wait_group 0;" ::: "memory");
        }
        __syncthreads();   // Pt written, Whs[jt&1] complete everywhere

        // ---- phase B: acc += P @ Wh  (FFMA2; unchanged R12 mapping) ----
        const float* Whs = WhsB[jt & 1];
        #pragma unroll 2
        for (int j = 0; j < 128; j++) {
            const float* pr = Pt + j * PSP + r;
            ull pd[4];
            #pragma unroll
            for (int u = 0; u < 4; u++) pd[u] = splat2(pr[32 * u]);
            const float* wr = Whs + j * PSW + 4 * c;
            float4 w0 = *(const float4*)(wr);
            float4 w1 = *(const float4*)(wr + 64);
            ull wv[4];
            wv[0] = asu2(make_float2(w0.x, w0.y));
            wv[1] = asu2(make_float2(w0.z, w0.w));
            wv[2] = asu2(make_float2(w1.x, w1.y));
            wv[3] = asu2(make_float2(w1.z, w1.w));
            #pragma unroll
            for (int u = 0; u < 4; u++)
                #pragma unroll
                for (int k = 0; k < 4; k++)
                    fma2(acc[u][k], pd[u], wv[k]);
        }
        __syncthreads();   // Pt/Whs[jt&1] consumed before reuse
    }

    // ---- rowsums ----
    #pragma unroll
    for (int s = 0; s < 8; s++) {
        float v = rsum[s];
        #pragma unroll
        for (int d = 16; d; d >>= 1) v += __shfl_xor_sync(0xffffffffu, v, d);
        if (lane == 0) rs[s * 16 + warp] = v;
    }
    __syncthreads();

    // ---- epilogue: normalize, LayerNorm, leaky (unchanged R12) ----
    #pragma unroll
    for (int u = 0; u < 4; u++) {
        int i = r + 32 * u;
        float inv = 1.f / rs[i];
        float2 v[4];
        float s = 0.f, sq = 0.f;
        #pragma unroll
        for (int k = 0; k < 4; k++) {
            float2 a2v = asf2(acc[u][k]);
            v[k].x = a2v.x * inv; v[k].y = a2v.y * inv;
            s += v[k].x + v[k].y;
            sq = fmaf(v[k].x, v[k].x, fmaf(v[k].y, v[k].y, sq));
        }
        #pragma unroll
        for (int d = 1; d < 16; d <<= 1) {
            s  += __shfl_xor_sync(0xffffffffu, s,  d);
            sq += __shfl_xor_sync(0xffffffffu, sq, d);
        }
        float mu   = s * (1.f / 128.f);
        float rstd = rsqrtf(sq * (1.f / 128.f) - mu * mu + EPS);
        float* op = out + (size_t)(b * NN + it * 128 + i) * FF;
        float4 y0, y1;
        y0.x = (v[0].x - mu) * rstd; y0.x = (y0.x >= 0.f) ? y0.x : ALPHA * y0.x;
        y0.y = (v[0].y - mu) * rstd; y0.y = (y0.y >= 0.f) ? y0.y : ALPHA * y0.y;
        y0.z = (v[1].x - mu) * rstd; y0.z = (y0.z >= 0.f) ? y0.z : ALPHA * y0.z;
        y0.w = (v[1].y - mu) * rstd; y0.w = (y0.w >= 0.f) ? y0.w : ALPHA * y0.w;
        y1.x = (v[2].x - mu) * rstd; y1.x = (y1.x >= 0.f) ? y1.x : ALPHA * y1.x;
        y1.y = (v[2].y - mu) * rstd; y1.y = (y1.y >= 0.f) ? y1.y : ALPHA * y1.y;
        y1.z = (v[3].x - mu) * rstd; y1.z = (y1.z >= 0.f) ? y1.z : ALPHA * y1.z;
        y1.w = (v[3].y - mu) * rstd; y1.w = (y1.w >= 0.f) ? y1.w : ALPHA * y1.w;
        *(float4*)(op + 4 * c)      = y0;
        *(float4*)(op + 4 * c + 64) = y1;
    }
}

// ---------------------------------------------------------------------------
extern "C" void kernel_launch(void* const* d_in, const int* in_sizes, int n_in,
                              void* d_out, int out_size) {
    const float* h    = (const float*)d_in[0];
    const int*   adj  = (const int*)  d_in[1];
    const float* W    = (const float*)d_in[2];
    const float* bias = (const float*)d_in[3];
    const float* aw   = (const float*)d_in[4];
    float*       out  = (float*)d_out;

    const int smem1 = (128 * PD + 128 * PS) * (int)sizeof(float);        // 199,680 B
    const int smem2 = (128 * PSP + 2 * 128 * PSW) * (int)sizeof(float);  // 201,216 B

    cudaFuncSetAttribute(gat_k1, cudaFuncAttributeMaxDynamicSharedMemorySize, smem1);
    cudaFuncSetAttribute(gat_k2, cudaFuncAttributeMaxDynamicSharedMemorySize, smem2);

    gat_k1<<<128, 256, smem1>>>(h, W, bias, aw);
    gat_k2<<<BB * 16, 512, smem2>>>(adj, out);
}